// round 14
// baseline (speedup 1.0000x reference)
#include <cuda_runtime.h>
#include <cuda_bf16.h>

#define NN 2048
#define HH 16
#define FIN 128
#define NBLK 128
#define NTHR 1024
#define GSZ (NBLK * NTHR)

// Output layout (float32): node_out [2048*2], edge_out [2048^2], start [2048^2], end [2048^2]
#define OFF_NODE  0
#define OFF_EDGE  4096
#define OFF_START (4096 + 4194304)
#define OFF_END   (4096 + 4194304 + 4194304)

// Scratch (static __device__: zero at load; every launch leaves them re-zeroed
// so CUDA-graph replays are deterministic).
__device__ float g_xw1[NN * HH];
__device__ float g_deg[NN];        // reset in P4
__device__ float g_agg1[NN * HH];  // read+reset in P2
__device__ float g_xw2[NN * 2];
__device__ float g_agg2[NN * 2];   // read+reset in P4
__device__ float g_A[NN * HH];
__device__ float g_Bb[NN * HH];
__device__ unsigned g_bar;
__device__ unsigned g_gen;

// ---------------------------------------------------------------------------
// Grid-wide barrier. Valid because NBLK=128 <= 148 SMs => all blocks co-resident.
__device__ __forceinline__ void gridbar(unsigned target_gen) {
    __syncthreads();
    if (threadIdx.x == 0) {
        __threadfence();
        unsigned a = atomicAdd(&g_bar, 1u);
        if (a == NBLK - 1) {
            g_bar = 0;
            __threadfence();
            atomicAdd(&g_gen, 1u);             // release
        } else {
            while (*(volatile unsigned*)&g_gen < target_gen) { }
        }
    }
    __syncthreads();
}

// Vector reductions (sm_90+): one LTS op for 4 / 2 floats.
__device__ __forceinline__ void red_add_v4(float* p, float a, float b, float c, float d) {
    asm volatile("red.global.add.v4.f32 [%0], {%1, %2, %3, %4};"
                 :: "l"(p), "f"(a), "f"(b), "f"(c), "f"(d) : "memory");
}
__device__ __forceinline__ void red_add_v2(float* p, float a, float b) {
    asm volatile("red.global.add.v2.f32 [%0], {%1, %2};"
                 :: "l"(p), "f"(a), "f"(b) : "memory");
}

// Dtype sniff: edge values < 2048 => for int64 all odd 32-bit words are zero.
__device__ __forceinline__ bool is_i64(const void* ei) {
    const uint4* p = (const uint4*)ei;
    uint4 a = __ldg(p), b = __ldg(p + 1);
    return ((a.y | a.w | b.y | b.w) == 0u);
}
__device__ __forceinline__ int edge_at(const void* ei, bool i64, long long idx) {
    if (i64) return (int)__ldg((const long long*)ei + idx);
    return __ldg((const int*)ei + idx);
}

// ---------------------------------------------------------------------------
__global__ void __launch_bounds__(NTHR) k_all(
    const float* __restrict__ x, const void* __restrict__ ei, int E,
    const float* __restrict__ W1, const float* __restrict__ b1,
    const float* __restrict__ W2, const float* __restrict__ b2,
    const float* __restrict__ Wc1, const float* __restrict__ bc1,
    const float* __restrict__ Wc2, const float* __restrict__ bc2,
    float* __restrict__ out)
{
    __shared__ float sW[FIN * HH];   // W1 (P0, blocks < 32)
    __shared__ float sWc1[32 * HH];  // Wc1 (P2)
    __shared__ float sA[32 * HH];    // A tile (P3)
    __shared__ unsigned s_gen0;

    int t = threadIdx.x, b = blockIdx.x;
    int gtid = b * NTHR + t;
    if (t == 0) s_gen0 = *(volatile unsigned*)&g_gen;
    if (b < 32)
        for (int idx = t; idx < FIN * HH; idx += NTHR) sW[idx] = W1[idx];
    for (int idx = t; idx < 32 * HH; idx += NTHR) sWc1[idx] = Wc1[idx];
    __syncthreads();
    unsigned gen0 = s_gen0;
    bool i64 = is_i64(ei);

    // ---- P0 (3-way block split):
    //   blocks [0,32):   xw1 = x@W1 (one output per thread)
    //   blocks [32,64):  degree counting (2 edges/thread)
    //   blocks [64,128): start/end index arrays (pure functions, 33MB, no deps)
    if (b < 32) {
        int row = gtid >> 4, col = gtid & 15;
        const float4* xr4 = (const float4*)(x + row * FIN);
        float acc = 0.0f;
#pragma unroll
        for (int k4 = 0; k4 < FIN / 4; k4++) {
            float4 xv = __ldg(xr4 + k4);
            acc = fmaf(xv.x, sW[(k4 * 4 + 0) * HH + col], acc);
            acc = fmaf(xv.y, sW[(k4 * 4 + 1) * HH + col], acc);
            acc = fmaf(xv.z, sW[(k4 * 4 + 2) * HH + col], acc);
            acc = fmaf(xv.w, sW[(k4 * 4 + 3) * HH + col], acc);
        }
        g_xw1[gtid] = acc;
    } else if (b < 64) {
        int g = (b - 32) * NTHR + t;          // [0, 32768)
        int e0 = g * 2;
        if (e0 < E) {
            int d0, d1;
            if (i64) {
                longlong2 v = __ldg((const longlong2*)((const long long*)ei + E + e0));
                d0 = (int)v.x; d1 = (int)v.y;
            } else {
                int2 v = __ldg((const int2*)((const int*)ei + E + e0));
                d0 = v.x; d1 = v.y;
            }
            atomicAdd(&g_deg[d0], 1.0f);
            if (e0 + 1 < E) atomicAdd(&g_deg[d1], 1.0f);
        }
    } else {
        int g = (b - 64) * NTHR + t;          // [0, 65536)
        float4* s4 = (float4*)(out + OFF_START);
        float4* e4 = (float4*)(out + OFF_END);
#pragma unroll
        for (int rep = 0; rep < 16; rep++) {
            int k4 = g + rep * 65536;         // [0, 1048576)
            int k = k4 * 4;
            float fi = (float)(k >> 11);
            int j = k & 2047;
            s4[k4] = make_float4(fi, fi, fi, fi);
            e4[k4] = make_float4((float)j, (float)(j + 1), (float)(j + 2), (float)(j + 3));
        }
    }
    gridbar(gen0 + 1);

    // ---- P1: 2 threads per edge: agg1[d] += xw1[s]*dinv[s] via red.v4 ----
    {
        int e = gtid >> 1, half = gtid & 1;   // GSZ == 2E exactly
        int s = edge_at(ei, i64, e);
        int d = edge_at(ei, i64, (long long)E + e);
        float dis = rsqrtf(g_deg[s] + 1.0f);
        const float4* xs = (const float4*)(g_xw1 + s * HH) + half * 2;
        float* ad = g_agg1 + d * HH + half * 8;
        float4 v0 = __ldg(xs), v1 = __ldg(xs + 1);
        red_add_v4(ad,     v0.x * dis, v0.y * dis, v0.z * dis, v0.w * dis);
        red_add_v4(ad + 4, v1.x * dis, v1.y * dis, v1.z * dis, v1.w * dis);
    }
    gridbar(gen0 + 2);

    // ---- P2: warp-per-node (warps 0-15 of each block): h, A, Bb, xw2 ----
    {
        int warp = t >> 5, lane = t & 31;
        if (warp < 16) {
            int i = b * 16 + warp;            // 128*16 = 2048 nodes
            int o = lane & 15, half = lane >> 4;  // 0 -> A, 1 -> Bb
            float wreg[HH];
#pragma unroll
            for (int c = 0; c < HH; c++) wreg[c] = sWc1[(half * HH + c) * HH + o];
            float w2reg[HH];
            if (lane < 2) {
#pragma unroll
                for (int c = 0; c < HH; c++) w2reg[c] = __ldg(W2 + c * 2 + lane);
            }
            float degi = g_deg[i] + 1.0f;
            float di = rsqrtf(degi);
            float ds = di * di;
            float myhv = 0.0f;
            if (lane < HH) {
                float v = di * g_agg1[i * HH + lane] + ds * g_xw1[i * HH + lane] + __ldg(b1 + lane);
                g_agg1[i * HH + lane] = 0.0f;  // reset for next replay
                myhv = fmaxf(v, 0.0f);
            }
            float acc = half ? __ldg(bc1 + o) : 0.0f;
            float acc2 = 0.0f;
#pragma unroll
            for (int c = 0; c < HH; c++) {
                float hc = __shfl_sync(0xffffffffu, myhv, c);
                acc = fmaf(hc, wreg[c], acc);
                if (lane < 2) acc2 = fmaf(hc, w2reg[c], acc2);
            }
            if (half == 0) g_A[i * HH + o] = acc;
            else           g_Bb[i * HH + o] = acc;
            if (lane < 2)  g_xw2[i * 2 + lane] = acc2;
        }
    }
    gridbar(gen0 + 3);

    // ---- P3: agg2 (thread-per-edge, red.v2), then edge_out tile ----
    {
        if (gtid < E) {
            int s = edge_at(ei, i64, gtid);
            int d = edge_at(ei, i64, (long long)E + gtid);
            float dis = rsqrtf(g_deg[s] + 1.0f);
            float2 xv = *(const float2*)(g_xw2 + s * 2);
            red_add_v2(g_agg2 + d * 2, xv.x * dis, xv.y * dis);
        }
        // edge tile: bx in {0,1} selects 1024 j's (1/thread), by in [0,64) -> 32 i's
        int bx = b & 1, by = b >> 1;
        int j = bx * 1024 + t;
        int i0 = by * 32;
        if (t < 32 * HH) sA[t] = g_A[i0 * HH + t];
        float4 w[4];
#pragma unroll
        for (int q = 0; q < 4; q++) w[q] = *(const float4*)(Wc2 + q * 4);
        float bb = bc2[0];
        float4 B[4];
#pragma unroll
        for (int q = 0; q < 4; q++) B[q] = *(const float4*)(g_Bb + j * HH + q * 4);
        __syncthreads();
        float* oe = out + OFF_EDGE + (long long)i0 * NN + j;
#pragma unroll 4
        for (int ii = 0; ii < 32; ii++) {
            const float4* a4 = (const float4*)(sA + ii * HH);
            float acc = bb;
#pragma unroll
            for (int q = 0; q < 4; q++) {
                float4 a = a4[q];
                acc = fmaf(fmaxf(a.x + B[q].x, 0.0f), w[q].x, acc);
                acc = fmaf(fmaxf(a.y + B[q].y, 0.0f), w[q].y, acc);
                acc = fmaf(fmaxf(a.z + B[q].z, 0.0f), w[q].z, acc);
                acc = fmaf(fmaxf(a.w + B[q].w, 0.0f), w[q].w, acc);
            }
            float p = __expf(-acc);
            oe[ii * NN] = __fdividef(1.0f, 1.0f + p);
        }
    }
    gridbar(gen0 + 4);

    // ---- P4: node_out + scratch resets (blocks 0..3, 1024 threads each) ----
    if (b < 4) {
        int i = b * 512 + (t >> 1);
        int c = t & 1;
        float degi = g_deg[i] + 1.0f;
        float di = rsqrtf(degi);
        float ds = di * di;
        out[OFF_NODE + i * 2 + c] =
            di * g_agg2[i * 2 + c] + ds * g_xw2[i * 2 + c] + __ldg(b2 + c);
        g_agg2[i * 2 + c] = 0.0f;
        if (c == 0) g_deg[i] = 0.0f;
    }
}

// ---------------------------------------------------------------------------
extern "C" void kernel_launch(void* const* d_in, const int* in_sizes, int n_in,
                              void* d_out, int out_size) {
    const float* x   = (const float*)d_in[0];
    const void*  ei  = d_in[1];
    const float* W1  = (const float*)d_in[2];
    const float* b1  = (const float*)d_in[3];
    const float* W2  = (const float*)d_in[4];
    const float* b2  = (const float*)d_in[5];
    const float* Wc1 = (const float*)d_in[6];
    const float* bc1 = (const float*)d_in[7];
    const float* Wc2 = (const float*)d_in[8];
    const float* bc2 = (const float*)d_in[9];
    float* out = (float*)d_out;

    int E = in_sizes[1] / 2;

    k_all<<<NBLK, NTHR>>>(x, ei, E, W1, b1, W2, b2, Wc1, bc1, Wc2, bc2, out);
}